// round 7
// baseline (speedup 1.0000x reference)
#include <cuda_runtime.h>
#include <math.h>

#define BATCH      512       // chains (fixed by setup_inputs)
#define PAIRS      256       // threads process chain pairs (b, b+256)
#define CHUNK_RES  4         // residues per chunk (12 points)
#define MAXK       1024      // chunks per chain supported

typedef unsigned long long u64;

// Scratch frames (packed pairs), layout [k][j][pair]. L2-resident.
__device__ u64 g_chunk [MAXK * 12 * PAIRS];
__device__ u64 g_prefix[MAXK * 12 * PAIRS];

// ---------- packed f32x2 primitives ----------
__device__ __forceinline__ u64 pk(float lo, float hi) {
    u64 r; asm("mov.b64 %0, {%1, %2};" : "=l"(r) : "f"(lo), "f"(hi)); return r;
}
__device__ __forceinline__ void upk(u64 v, float& lo, float& hi) {
    asm("mov.b64 {%0, %1}, %2;" : "=f"(lo), "=f"(hi) : "l"(v));
}
__device__ __forceinline__ u64 f2fma(u64 a, u64 b, u64 c) {
    u64 r; asm("fma.rn.f32x2 %0, %1, %2, %3;" : "=l"(r) : "l"(a), "l"(b), "l"(c)); return r;
}
__device__ __forceinline__ u64 f2mul(u64 a, u64 b) {
    u64 r; asm("mul.rn.f32x2 %0, %1, %2;" : "=l"(r) : "l"(a), "l"(b)); return r;
}

// Packed frame: m[0..8] = rotation row-major, m[9..11] = translation.
struct PFrame { u64 m[12]; };

__device__ __forceinline__ void pf_identity(PFrame& f) {
    u64 one = pk(1.f, 1.f), zero = pk(0.f, 0.f);
    f.m[0] = one;  f.m[1] = zero; f.m[2] = zero;
    f.m[3] = zero; f.m[4] = one;  f.m[5] = zero;
    f.m[6] = zero; f.m[7] = zero; f.m[8] = one;
    f.m[9] = zero; f.m[10] = zero; f.m[11] = zero;
}

// Packed geometry invariants for one point-slot q of a chain pair.
struct PGeom { u64 ux2, kk2, nkk2, L2; };

// F = F ∘ G(s,c): u=(ux,c*kk,s*kk), n=(0,-s,c), v=n×u=(-kk,c*ux,s*ux), t_G=L*u
__device__ __forceinline__ void extend_p(PFrame& f, u64 s2, u64 c2, u64 ns2,
                                         const PGeom& g) {
    u64 ck2  = f2mul(c2, g.kk2);
    u64 sk2  = f2mul(s2, g.kk2);
    u64 cux2 = f2mul(c2, g.ux2);
    u64 sux2 = f2mul(s2, g.ux2);
    #pragma unroll
    for (int j = 0; j < 3; j++) {
        u64 r0 = f.m[3*j], r1 = f.m[3*j+1], r2 = f.m[3*j+2];
        u64 a0 = f2fma(r0, g.ux2, f2fma(r1, ck2,  f2mul(r2, sk2)));
        u64 a1 = f2fma(r1, cux2,  f2fma(r2, sux2, f2mul(r0, g.nkk2)));
        u64 a2 = f2fma(r2, c2,    f2mul(r1, ns2));
        f.m[9+j] = f2fma(g.L2, a0, f.m[9+j]);
        f.m[3*j] = a0; f.m[3*j+1] = a1; f.m[3*j+2] = a2;
    }
}

// f = f ∘ g
__device__ __forceinline__ void compose_p(PFrame& f, const PFrame& g) {
    u64 n[12];
    #pragma unroll
    for (int j = 0; j < 3; j++) {
        u64 r0 = f.m[3*j], r1 = f.m[3*j+1], r2 = f.m[3*j+2];
        n[9+j]  = f2fma(r0, g.m[9], f2fma(r1, g.m[10], f2fma(r2, g.m[11], f.m[9+j])));
        #pragma unroll
        for (int i = 0; i < 3; i++)
            n[3*j+i] = f2fma(r0, g.m[i], f2fma(r1, g.m[3+i], f2mul(r2, g.m[6+i])));
    }
    #pragma unroll
    for (int j = 0; j < 12; j++) f.m[j] = n[j];
}

__device__ __forceinline__ void store_pf(u64* base, const PFrame& f) {
    #pragma unroll
    for (int j = 0; j < 12; j++) base[j * PAIRS] = f.m[j];
}
__device__ __forceinline__ void load_pf(const u64* base, PFrame& f) {
    #pragma unroll
    for (int j = 0; j < 12; j++) f.m[j] = base[j * PAIRS];
}

__device__ __forceinline__ PFrame shfl_up_pf(const PFrame& f, int d) {
    PFrame o;
    #pragma unroll
    for (int j = 0; j < 12; j++)
        o.m[j] = __shfl_up_sync(0xFFFFFFFF, f.m[j], d);
    return o;
}

// Host-computed geometry constants (scalar, per geometry index 0..2)
struct Geom { float ux[3]; float kk[3]; float L[3]; };

// Point m = 3l+q of chain b uses flat element D[l*1536 + q*512 + b],
// geometry index (q*512 + b) % 3.
__device__ __forceinline__ void pair_geom(const Geom& gm, int b, PGeom pg[3]) {
    int gA[3] = { b % 3, (b + 2) % 3, (b + 1) % 3 };
    int bb = b + PAIRS;
    int gB[3] = { bb % 3, (bb + 2) % 3, (bb + 1) % 3 };
    #pragma unroll
    for (int q = 0; q < 3; q++) {
        pg[q].ux2  = pk(gm.ux[gA[q]],  gm.ux[gB[q]]);
        pg[q].kk2  = pk(gm.kk[gA[q]],  gm.kk[gB[q]]);
        pg[q].nkk2 = pk(-gm.kk[gA[q]], -gm.kk[gB[q]]);
        pg[q].L2   = pk(gm.L[gA[q]],   gm.L[gB[q]]);
    }
}

__device__ __forceinline__ void sincos_pair(float dA, float dB,
                                            u64& s2, u64& c2, u64& ns2) {
    float sA, cA, sB, cB;
    __sincosf(dA, &sA, &cA);
    __sincosf(dB, &sB, &cB);
    s2  = pk(sA, sB);
    c2  = pk(cA, cB);
    ns2 = pk(-sA, -sB);
}

// Kernel A: per-(pair, chunk) product of the chunk's step transforms.
__global__ __launch_bounds__(128)
void kA(const float* __restrict__ dih, Geom gm, int K, int LRES) {
    int idx = blockIdx.x * blockDim.x + threadIdx.x;
    if (idx >= PAIRS * K) return;
    int b = idx & (PAIRS - 1);
    int k = idx >> 8;

    PGeom pg[3];
    pair_geom(gm, b, pg);

    PFrame f; pf_identity(f);
    int l0 = k * CHUNK_RES;
    int l1 = min(LRES, l0 + CHUNK_RES);
    for (int l = l0; l < l1; l++) {
        const float* dp = dih + (size_t)l * (3 * BATCH) + b;
        float dA0 = dp[0],         dB0 = dp[PAIRS];
        float dA1 = dp[BATCH],     dB1 = dp[BATCH + PAIRS];
        float dA2 = dp[2 * BATCH], dB2 = dp[2 * BATCH + PAIRS];
        u64 s2, c2, ns2;
        sincos_pair(dA0, dB0, s2, c2, ns2); extend_p(f, s2, c2, ns2, pg[0]);
        sincos_pair(dA1, dB1, s2, c2, ns2); extend_p(f, s2, c2, ns2, pg[1]);
        sincos_pair(dA2, dB2, s2, c2, ns2); extend_p(f, s2, c2, ns2, pg[2]);
    }
    store_pf(g_chunk + (size_t)k * 12 * PAIRS + b, f);
}

// Scan: one warp per pair. Lane ss owns chunks [ss*SUPW, (ss+1)*SUPW):
// builds its superchunk product, Kogge-Stone scan over lanes, then serially
// DISTRIBUTES exclusive prefixes for every chunk it owns (kC has no fixup).
__global__ __launch_bounds__(128)
void kScan(int K, int SUPW, int NSUP) {
    int warp = (blockIdx.x * blockDim.x + threadIdx.x) >> 5;
    int lane = threadIdx.x & 31;
    if (warp >= PAIRS) return;
    int b = warp;

    int k0 = lane * SUPW;
    int k1 = min(K, k0 + SUPW);

    // Build superchunk product (pairwise to shorten the dependency chain).
    PFrame f; pf_identity(f);
    if (lane < NSUP) {
        int k = k0;
        bool first = true;
        while (k < k1) {
            PFrame a; load_pf(g_chunk + (size_t)k * 12 * PAIRS + b, a);
            if (k + 1 < k1) {
                PFrame c2; load_pf(g_chunk + (size_t)(k + 1) * 12 * PAIRS + b, c2);
                compose_p(a, c2);
                k += 2;
            } else k += 1;
            if (first) { f = a; first = false; }
            else       { compose_p(f, a); }
        }
    }

    // Kogge-Stone inclusive scan over lanes.
    #pragma unroll
    for (int d = 1; d < 32; d <<= 1) {
        PFrame left = shfl_up_pf(f, d);
        PFrame t = left;
        compose_p(t, f);
        if (lane >= d) f = t;
    }

    // Exclusive lane prefix.
    PFrame run = shfl_up_pf(f, 1);
    if (lane == 0) pf_identity(run);

    // Distribute: exclusive prefix for every chunk this lane owns.
    if (lane < NSUP) {
        for (int k = k0; k < k1; k++) {
            store_pf(g_prefix + (size_t)k * 12 * PAIRS + b, run);
            PFrame g; load_pf(g_chunk + (size_t)k * 12 * PAIRS + b, g);
            compose_p(run, g);
        }
    }
}

// Kernel C: load own chunk prefix (no fixup), replay chunk, emit coordinates.
__global__ __launch_bounds__(128)
void kC(const float* __restrict__ dih, Geom gm, float* __restrict__ out,
        int K, int LRES) {
    int idx = blockIdx.x * blockDim.x + threadIdx.x;
    if (idx >= PAIRS * K) return;
    int b = idx & (PAIRS - 1);
    int k = idx >> 8;

    PGeom pg[3];
    pair_geom(gm, b, pg);

    PFrame f;
    load_pf(g_prefix + (size_t)k * 12 * PAIRS + b, f);

    int l0 = k * CHUNK_RES;
    int l1 = min(LRES, l0 + CHUNK_RES);
    for (int l = l0; l < l1; l++) {
        const float* dp = dih + (size_t)l * (3 * BATCH) + b;
        float dA0 = dp[0],         dB0 = dp[PAIRS];
        float dA1 = dp[BATCH],     dB1 = dp[BATCH + PAIRS];
        float dA2 = dp[2 * BATCH], dB2 = dp[2 * BATCH + PAIRS];
        u64 s2, c2, ns2;
        float* oA = out + ((size_t)(3 * l) * BATCH + b) * 3;
        float* oB = oA + (size_t)PAIRS * 3;

        #pragma unroll
        for (int q = 0; q < 3; q++) {
            float dA = (q == 0) ? dA0 : (q == 1 ? dA1 : dA2);
            float dB = (q == 0) ? dB0 : (q == 1 ? dB1 : dB2);
            sincos_pair(dA, dB, s2, c2, ns2);
            extend_p(f, s2, c2, ns2, pg[q]);
            float txA, txB, tyA, tyB, tzA, tzB;
            upk(f.m[9],  txA, txB);
            upk(f.m[10], tyA, tyB);
            upk(f.m[11], tzA, tzB);
            oA[0] = txA; oA[1] = tyA; oA[2] = tzA;
            oB[0] = txB; oB[1] = tyB; oB[2] = tzB;
            oA += (size_t)BATCH * 3;
            oB += (size_t)BATCH * 3;
        }
    }
}

extern "C" void kernel_launch(void* const* d_in, const int* in_sizes, int n_in,
                              void* d_out, int out_size) {
    const float* dih = (const float*)d_in[0];
    float* out = (float*)d_out;

    int Npts = in_sizes[0] / BATCH;
    int LRES = Npts / 3;
    int K = (LRES + CHUNK_RES - 1) / CHUNK_RES;
    if (K > MAXK) K = MAXK;
    int SUPW = (K + 31) / 32;
    int NSUP = (K + SUPW - 1) / SUPW;

    const double PI = 3.14159265358979323846;
    const float BL[3] = {145.801f, 152.326f, 132.868f};
    const float BA[3] = {2.124f, 1.941f, 2.028f};
    Geom gm;
    for (int d = 0; d < 3; d++) {
        double a  = PI - (double)BA[d];
        double rc = (double)BL[d] * cos(a);
        double rs = (double)BL[d] * sin(a);
        double L  = sqrt(rc * rc + rs * rs);
        gm.ux[d] = (float)(rc / L);
        gm.kk[d] = (float)(rs / L);
        gm.L[d]  = (float)L;
    }

    int nAC = PAIRS * K;
    kA   <<<(nAC + 127) / 128, 128>>>(dih, gm, K, LRES);
    kScan<<<(PAIRS * 32 + 127) / 128, 128>>>(K, SUPW, NSUP);
    kC   <<<(nAC + 127) / 128, 128>>>(dih, gm, out, K, LRES);
}

// round 8
// speedup vs baseline: 1.7989x; 1.7989x over previous
#include <cuda_runtime.h>
#include <math.h>

#define BATCH      512       // chains (fixed by setup_inputs)
#define PAIRS      256       // threads process chain pairs (b, b+256)
#define CHUNK_RES  8         // residues per chunk (24 points)
#define CHUNK_PTS  (CHUNK_RES * 3)
#define MAXK       256       // chunks per chain supported (2048 residues)

typedef unsigned long long u64;

// Scratch (packed pairs). g_chunk/g_sprefix: [k][j][pair].
// g_tloc: per-step chunk-local translations, [k][step][j][pair].
__device__ u64 g_chunk  [MAXK * 12 * PAIRS];
__device__ u64 g_sprefix[32   * 12 * PAIRS];
__device__ u64 g_tloc   [MAXK * CHUNK_PTS * 3 * PAIRS];   // 37.7 MB

// ---------- packed f32x2 primitives ----------
__device__ __forceinline__ u64 pk(float lo, float hi) {
    u64 r; asm("mov.b64 %0, {%1, %2};" : "=l"(r) : "f"(lo), "f"(hi)); return r;
}
__device__ __forceinline__ void upk(u64 v, float& lo, float& hi) {
    asm("mov.b64 {%0, %1}, %2;" : "=f"(lo), "=f"(hi) : "l"(v));
}
__device__ __forceinline__ u64 f2fma(u64 a, u64 b, u64 c) {
    u64 r; asm("fma.rn.f32x2 %0, %1, %2, %3;" : "=l"(r) : "l"(a), "l"(b), "l"(c)); return r;
}
__device__ __forceinline__ u64 f2mul(u64 a, u64 b) {
    u64 r; asm("mul.rn.f32x2 %0, %1, %2;" : "=l"(r) : "l"(a), "l"(b)); return r;
}

// Packed frame: m[0..8] = rotation row-major, m[9..11] = translation.
struct PFrame { u64 m[12]; };

__device__ __forceinline__ void pf_identity(PFrame& f) {
    u64 one = pk(1.f, 1.f), zero = pk(0.f, 0.f);
    f.m[0] = one;  f.m[1] = zero; f.m[2] = zero;
    f.m[3] = zero; f.m[4] = one;  f.m[5] = zero;
    f.m[6] = zero; f.m[7] = zero; f.m[8] = one;
    f.m[9] = zero; f.m[10] = zero; f.m[11] = zero;
}

struct PGeom { u64 ux2, kk2, nkk2, L2; };

// F = F ∘ G(s,c): u=(ux,c*kk,s*kk), n=(0,-s,c), v=n×u=(-kk,c*ux,s*ux), t_G=L*u
__device__ __forceinline__ void extend_p(PFrame& f, u64 s2, u64 c2, u64 ns2,
                                         const PGeom& g) {
    u64 ck2  = f2mul(c2, g.kk2);
    u64 sk2  = f2mul(s2, g.kk2);
    u64 cux2 = f2mul(c2, g.ux2);
    u64 sux2 = f2mul(s2, g.ux2);
    #pragma unroll
    for (int j = 0; j < 3; j++) {
        u64 r0 = f.m[3*j], r1 = f.m[3*j+1], r2 = f.m[3*j+2];
        u64 a0 = f2fma(r0, g.ux2, f2fma(r1, ck2,  f2mul(r2, sk2)));
        u64 a1 = f2fma(r1, cux2,  f2fma(r2, sux2, f2mul(r0, g.nkk2)));
        u64 a2 = f2fma(r2, c2,    f2mul(r1, ns2));
        f.m[9+j] = f2fma(g.L2, a0, f.m[9+j]);
        f.m[3*j] = a0; f.m[3*j+1] = a1; f.m[3*j+2] = a2;
    }
}

// f = f ∘ g
__device__ __forceinline__ void compose_p(PFrame& f, const PFrame& g) {
    u64 n[12];
    #pragma unroll
    for (int j = 0; j < 3; j++) {
        u64 r0 = f.m[3*j], r1 = f.m[3*j+1], r2 = f.m[3*j+2];
        n[9+j]  = f2fma(r0, g.m[9], f2fma(r1, g.m[10], f2fma(r2, g.m[11], f.m[9+j])));
        #pragma unroll
        for (int i = 0; i < 3; i++)
            n[3*j+i] = f2fma(r0, g.m[i], f2fma(r1, g.m[3+i], f2mul(r2, g.m[6+i])));
    }
    #pragma unroll
    for (int j = 0; j < 12; j++) f.m[j] = n[j];
}

__device__ __forceinline__ void store_pf(u64* base, const PFrame& f) {
    #pragma unroll
    for (int j = 0; j < 12; j++) base[j * PAIRS] = f.m[j];
}
__device__ __forceinline__ void load_pf(const u64* base, PFrame& f) {
    #pragma unroll
    for (int j = 0; j < 12; j++) f.m[j] = base[j * PAIRS];
}

__device__ __forceinline__ PFrame shfl_up_pf(const PFrame& f, int d) {
    PFrame o;
    #pragma unroll
    for (int j = 0; j < 12; j++)
        o.m[j] = __shfl_up_sync(0xFFFFFFFF, f.m[j], d);
    return o;
}

struct Geom { float ux[3]; float kk[3]; float L[3]; };

// Point m = 3l+q of chain b uses flat element D[l*1536 + q*512 + b],
// geometry index (q*512 + b) % 3.
__device__ __forceinline__ void pair_geom(const Geom& gm, int b, PGeom pg[3]) {
    int gA[3] = { b % 3, (b + 2) % 3, (b + 1) % 3 };
    int bb = b + PAIRS;
    int gB[3] = { bb % 3, (bb + 2) % 3, (bb + 1) % 3 };
    #pragma unroll
    for (int q = 0; q < 3; q++) {
        pg[q].ux2  = pk(gm.ux[gA[q]],  gm.ux[gB[q]]);
        pg[q].kk2  = pk(gm.kk[gA[q]],  gm.kk[gB[q]]);
        pg[q].nkk2 = pk(-gm.kk[gA[q]], -gm.kk[gB[q]]);
        pg[q].L2   = pk(gm.L[gA[q]],   gm.L[gB[q]]);
    }
}

__device__ __forceinline__ void sincos_pair(float dA, float dB,
                                            u64& s2, u64& c2, u64& ns2) {
    float sA, cA, sB, cB;
    __sincosf(dA, &sA, &cA);
    __sincosf(dB, &sB, &cB);
    s2  = pk(sA, sB);
    c2  = pk(cA, cB);
    ns2 = pk(-sA, -sB);
}

// Kernel A: chunk products + per-step chunk-local translations.
__global__ __launch_bounds__(128)
void kA(const float* __restrict__ dih, Geom gm, int K, int LRES) {
    int idx = blockIdx.x * blockDim.x + threadIdx.x;
    if (idx >= PAIRS * K) return;
    int b = idx & (PAIRS - 1);
    int k = idx >> 8;

    PGeom pg[3];
    pair_geom(gm, b, pg);

    PFrame f; pf_identity(f);
    u64* tb = g_tloc + ((size_t)k * CHUNK_PTS * 3) * PAIRS + b;
    int l0 = k * CHUNK_RES;
    int l1 = min(LRES, l0 + CHUNK_RES);
    for (int l = l0; l < l1; l++) {
        const float* dp = dih + (size_t)l * (3 * BATCH) + b;
        float dA0 = dp[0],         dB0 = dp[PAIRS];
        float dA1 = dp[BATCH],     dB1 = dp[BATCH + PAIRS];
        float dA2 = dp[2 * BATCH], dB2 = dp[2 * BATCH + PAIRS];
        u64 s2, c2, ns2;
        sincos_pair(dA0, dB0, s2, c2, ns2); extend_p(f, s2, c2, ns2, pg[0]);
        tb[0] = f.m[9]; tb[PAIRS] = f.m[10]; tb[2 * PAIRS] = f.m[11];
        tb += 3 * PAIRS;
        sincos_pair(dA1, dB1, s2, c2, ns2); extend_p(f, s2, c2, ns2, pg[1]);
        tb[0] = f.m[9]; tb[PAIRS] = f.m[10]; tb[2 * PAIRS] = f.m[11];
        tb += 3 * PAIRS;
        sincos_pair(dA2, dB2, s2, c2, ns2); extend_p(f, s2, c2, ns2, pg[2]);
        tb[0] = f.m[9]; tb[PAIRS] = f.m[10]; tb[2 * PAIRS] = f.m[11];
        tb += 3 * PAIRS;
    }
    store_pf(g_chunk + (size_t)k * 12 * PAIRS + b, f);
}

// Scan: one warp per pair (as in R6). Lane ss builds its superchunk product
// from SUPW chunk products (tree), Kogge-Stone over lanes, writes the
// EXCLUSIVE superchunk prefix.
__global__ __launch_bounds__(128)
void kScan(int K, int SUPW, int NSUP) {
    int warp = (blockIdx.x * blockDim.x + threadIdx.x) >> 5;
    int lane = threadIdx.x & 31;
    if (warp >= PAIRS) return;
    int b = warp;

    PFrame f; pf_identity(f);
    if (lane < NSUP) {
        int k0 = lane * SUPW;
        int k1 = min(K, k0 + SUPW);
        int k = k0;
        bool first = true;
        while (k < k1) {
            PFrame a; load_pf(g_chunk + (size_t)k * 12 * PAIRS + b, a);
            if (k + 1 < k1) {
                PFrame c2; load_pf(g_chunk + (size_t)(k + 1) * 12 * PAIRS + b, c2);
                compose_p(a, c2);
                k += 2;
            } else k += 1;
            if (first) { f = a; first = false; }
            else       { compose_p(f, a); }
        }
    }

    #pragma unroll
    for (int d = 1; d < 32; d <<= 1) {
        PFrame left = shfl_up_pf(f, d);
        PFrame t = left;
        compose_p(t, f);
        if (lane >= d) f = t;
    }

    PFrame ex = shfl_up_pf(f, 1);
    if (lane == 0) pf_identity(ex);

    if (lane < NSUP)
        store_pf(g_sprefix + (size_t)lane * 12 * PAIRS + b, ex);
}

// Kernel C: assemble chunk prefix (superchunk prefix + warp-uniform fixup
// composes), then emit coordinates via coord = R_pref * t_loc + t_pref.
// No sincos, no extend — prefix is constant so the loop is pure ILP.
__global__ __launch_bounds__(128)
void kC(float* __restrict__ out, int K, int LRES, int SUPW) {
    int idx = blockIdx.x * blockDim.x + threadIdx.x;
    if (idx >= PAIRS * K) return;
    int b = idx & (PAIRS - 1);
    int k = idx >> 8;
    int ss = k / SUPW;
    int k0 = ss * SUPW;

    PFrame f;
    load_pf(g_sprefix + (size_t)ss * 12 * PAIRS + b, f);
    for (int kk = k0; kk < k; kk++) {           // uniform across the warp
        PFrame g; load_pf(g_chunk + (size_t)kk * 12 * PAIRS + b, g);
        compose_p(f, g);
    }

    const u64* __restrict__ tb = g_tloc + ((size_t)k * CHUNK_PTS * 3) * PAIRS + b;
    int l0 = k * CHUNK_RES;
    int nsteps = (min(LRES, l0 + CHUNK_RES) - l0) * 3;
    float* oA = out + ((size_t)(3 * l0) * BATCH + b) * 3;
    float* oB = oA + (size_t)PAIRS * 3;

    #pragma unroll 3
    for (int i = 0; i < nsteps; i++) {
        u64 t0 = tb[0], t1 = tb[PAIRS], t2 = tb[2 * PAIRS];
        tb += 3 * PAIRS;
        u64 cx = f2fma(f.m[0], t0, f2fma(f.m[1], t1, f2fma(f.m[2], t2, f.m[9])));
        u64 cy = f2fma(f.m[3], t0, f2fma(f.m[4], t1, f2fma(f.m[5], t2, f.m[10])));
        u64 cz = f2fma(f.m[6], t0, f2fma(f.m[7], t1, f2fma(f.m[8], t2, f.m[11])));
        float xA, xB, yA, yB, zA, zB;
        upk(cx, xA, xB);
        upk(cy, yA, yB);
        upk(cz, zA, zB);
        oA[0] = xA; oA[1] = yA; oA[2] = zA;
        oB[0] = xB; oB[1] = yB; oB[2] = zB;
        oA += (size_t)BATCH * 3;
        oB += (size_t)BATCH * 3;
    }
}

extern "C" void kernel_launch(void* const* d_in, const int* in_sizes, int n_in,
                              void* d_out, int out_size) {
    const float* dih = (const float*)d_in[0];
    float* out = (float*)d_out;

    int Npts = in_sizes[0] / BATCH;
    int LRES = Npts / 3;
    int K = (LRES + CHUNK_RES - 1) / CHUNK_RES;
    if (K > MAXK) K = MAXK;
    int SUPW = (K + 31) / 32;
    int NSUP = (K + SUPW - 1) / SUPW;

    const double PI = 3.14159265358979323846;
    const float BL[3] = {145.801f, 152.326f, 132.868f};
    const float BA[3] = {2.124f, 1.941f, 2.028f};
    Geom gm;
    for (int d = 0; d < 3; d++) {
        double a  = PI - (double)BA[d];
        double rc = (double)BL[d] * cos(a);
        double rs = (double)BL[d] * sin(a);
        double L  = sqrt(rc * rc + rs * rs);
        gm.ux[d] = (float)(rc / L);
        gm.kk[d] = (float)(rs / L);
        gm.L[d]  = (float)L;
    }

    int nAC = PAIRS * K;
    kA   <<<(nAC + 127) / 128, 128>>>(dih, gm, K, LRES);
    kScan<<<(PAIRS * 32 + 127) / 128, 128>>>(K, SUPW, NSUP);
    kC   <<<(nAC + 127) / 128, 128>>>(out, K, LRES, SUPW);
}

// round 9
// speedup vs baseline: 2.3186x; 1.2889x over previous
#include <cuda_runtime.h>
#include <math.h>

#define BATCH      512       // fixed by the problem's setup_inputs
#define CHUNK_RES  8         // residues per chunk (24 points)
#define MAXK       512       // chunks per chain supported

// Scratch frames, layout [k][j][b] (12 floats per frame)
__device__ float g_chunk  [MAXK * 12 * BATCH];
__device__ float g_sprefix[32   * 12 * BATCH];

// Per-geometry constants: ux = rc/L, kk = rs/L, L (bond length)
struct Geom { float ux[3]; float kk[3]; float L[3]; };

struct Frame {
    float r00, r01, r02, r10, r11, r12, r20, r21, r22;
    float tx, ty, tz;
};

__device__ __forceinline__ void frame_identity(Frame& f) {
    f.r00 = 1.f; f.r01 = 0.f; f.r02 = 0.f;
    f.r10 = 0.f; f.r11 = 1.f; f.r12 = 0.f;
    f.r20 = 0.f; f.r21 = 0.f; f.r22 = 1.f;
    f.tx = 0.f; f.ty = 0.f; f.tz = 0.f;
}

// F = F ∘ G(s,c | geometry). Closed-form G:
//   u = (ux, c*kk, s*kk) (unit), n = (0,-s,c), v = n×u = (-kk, c*ux, s*ux), t_G = L*u
__device__ __forceinline__ void extend(Frame& f, float s, float c,
                                       float ux, float kk, float L) {
    float ck  = c * kk, sk  = s * kk;
    float cux = c * ux, sux = s * ux;
    float a00 = fmaf(f.r00, ux, fmaf(f.r01, ck, f.r02 * sk));
    float a10 = fmaf(f.r10, ux, fmaf(f.r11, ck, f.r12 * sk));
    float a20 = fmaf(f.r20, ux, fmaf(f.r21, ck, f.r22 * sk));
    float a01 = fmaf(f.r01, cux, fmaf(f.r02, sux, -f.r00 * kk));
    float a11 = fmaf(f.r11, cux, fmaf(f.r12, sux, -f.r10 * kk));
    float a21 = fmaf(f.r21, cux, fmaf(f.r22, sux, -f.r20 * kk));
    float a02 = fmaf(f.r02, c, -f.r01 * s);
    float a12 = fmaf(f.r12, c, -f.r11 * s);
    float a22 = fmaf(f.r22, c, -f.r21 * s);
    f.tx = fmaf(L, a00, f.tx);
    f.ty = fmaf(L, a10, f.ty);
    f.tz = fmaf(L, a20, f.tz);
    f.r00 = a00; f.r01 = a01; f.r02 = a02;
    f.r10 = a10; f.r11 = a11; f.r12 = a12;
    f.r20 = a20; f.r21 = a21; f.r22 = a22;
}

// f = f ∘ g
__device__ __forceinline__ void compose(Frame& f, const Frame& g) {
    float tx = fmaf(f.r00, g.tx, fmaf(f.r01, g.ty, fmaf(f.r02, g.tz, f.tx)));
    float ty = fmaf(f.r10, g.tx, fmaf(f.r11, g.ty, fmaf(f.r12, g.tz, f.ty)));
    float tz = fmaf(f.r20, g.tx, fmaf(f.r21, g.ty, fmaf(f.r22, g.tz, f.tz)));
    float a00 = fmaf(f.r00, g.r00, fmaf(f.r01, g.r10, f.r02 * g.r20));
    float a01 = fmaf(f.r00, g.r01, fmaf(f.r01, g.r11, f.r02 * g.r21));
    float a02 = fmaf(f.r00, g.r02, fmaf(f.r01, g.r12, f.r02 * g.r22));
    float a10 = fmaf(f.r10, g.r00, fmaf(f.r11, g.r10, f.r12 * g.r20));
    float a11 = fmaf(f.r10, g.r01, fmaf(f.r11, g.r11, f.r12 * g.r21));
    float a12 = fmaf(f.r10, g.r02, fmaf(f.r11, g.r12, f.r12 * g.r22));
    float a20 = fmaf(f.r20, g.r00, fmaf(f.r21, g.r10, f.r22 * g.r20));
    float a21 = fmaf(f.r20, g.r01, fmaf(f.r21, g.r11, f.r22 * g.r21));
    float a22 = fmaf(f.r20, g.r02, fmaf(f.r21, g.r12, f.r22 * g.r22));
    f.r00 = a00; f.r01 = a01; f.r02 = a02;
    f.r10 = a10; f.r11 = a11; f.r12 = a12;
    f.r20 = a20; f.r21 = a21; f.r22 = a22;
    f.tx = tx; f.ty = ty; f.tz = tz;
}

__device__ __forceinline__ void store_frame(float* base, const Frame& f) {
    base[0 * BATCH] = f.r00; base[1 * BATCH]  = f.r01; base[2 * BATCH]  = f.r02;
    base[3 * BATCH] = f.r10; base[4 * BATCH]  = f.r11; base[5 * BATCH]  = f.r12;
    base[6 * BATCH] = f.r20; base[7 * BATCH]  = f.r21; base[8 * BATCH]  = f.r22;
    base[9 * BATCH] = f.tx;  base[10 * BATCH] = f.ty;  base[11 * BATCH] = f.tz;
}

__device__ __forceinline__ void load_frame(const float* base, Frame& f) {
    f.r00 = base[0 * BATCH]; f.r01 = base[1 * BATCH];  f.r02 = base[2 * BATCH];
    f.r10 = base[3 * BATCH]; f.r11 = base[4 * BATCH];  f.r12 = base[5 * BATCH];
    f.r20 = base[6 * BATCH]; f.r21 = base[7 * BATCH];  f.r22 = base[8 * BATCH];
    f.tx  = base[9 * BATCH]; f.ty  = base[10 * BATCH]; f.tz  = base[11 * BATCH];
}

__device__ __forceinline__ Frame shfl_up_frame(const Frame& f, int d) {
    Frame o;
    o.r00 = __shfl_up_sync(0xFFFFFFFF, f.r00, d);
    o.r01 = __shfl_up_sync(0xFFFFFFFF, f.r01, d);
    o.r02 = __shfl_up_sync(0xFFFFFFFF, f.r02, d);
    o.r10 = __shfl_up_sync(0xFFFFFFFF, f.r10, d);
    o.r11 = __shfl_up_sync(0xFFFFFFFF, f.r11, d);
    o.r12 = __shfl_up_sync(0xFFFFFFFF, f.r12, d);
    o.r20 = __shfl_up_sync(0xFFFFFFFF, f.r20, d);
    o.r21 = __shfl_up_sync(0xFFFFFFFF, f.r21, d);
    o.r22 = __shfl_up_sync(0xFFFFFFFF, f.r22, d);
    o.tx  = __shfl_up_sync(0xFFFFFFFF, f.tx,  d);
    o.ty  = __shfl_up_sync(0xFFFFFFFF, f.ty,  d);
    o.tz  = __shfl_up_sync(0xFFFFFFFF, f.tz,  d);
    return o;
}

// Per-chain geometry: point m = 3l+q of chain b uses flat element
// D[l*1536 + q*512 + b], geometry index (q*512 + b) % 3.
__device__ __forceinline__ void chain_geom(const Geom& gm, int b,
                                           float* uxs, float* kks, float* Ls) {
    int g0 = b % 3;
    int g1 = (b + 2) % 3;
    int g2 = (b + 1) % 3;
    uxs[0] = gm.ux[g0]; kks[0] = gm.kk[g0]; Ls[0] = gm.L[g0];
    uxs[1] = gm.ux[g1]; kks[1] = gm.kk[g1]; Ls[1] = gm.L[g1];
    uxs[2] = gm.ux[g2]; kks[2] = gm.kk[g2]; Ls[2] = gm.L[g2];
}

// Kernel A: per-(chain, chunk) product of the chunk's step transforms.
__global__ __launch_bounds__(128)
void kA(const float* __restrict__ dih, Geom gm, int K, int LRES) {
    int idx = blockIdx.x * blockDim.x + threadIdx.x;
    if (idx >= BATCH * K) return;
    int b = idx & (BATCH - 1);
    int k = idx >> 9;

    float uxs[3], kks[3], Ls[3];
    chain_geom(gm, b, uxs, kks, Ls);

    Frame f; frame_identity(f);
    int l0 = k * CHUNK_RES;
    int l1 = min(LRES, l0 + CHUNK_RES);
    for (int l = l0; l < l1; l++) {
        const float* dp = dih + (size_t)l * (3 * BATCH) + b;
        float d0 = dp[0], d1 = dp[BATCH], d2 = dp[2 * BATCH];
        float s, c;
        __sincosf(d0, &s, &c); extend(f, s, c, uxs[0], kks[0], Ls[0]);
        __sincosf(d1, &s, &c); extend(f, s, c, uxs[1], kks[1], Ls[1]);
        __sincosf(d2, &s, &c); extend(f, s, c, uxs[2], kks[2], Ls[2]);
    }
    store_frame(g_chunk + (size_t)k * 12 * BATCH + b, f);
}

// Scan kernel: one warp per chain. Lane ss builds its superchunk product from
// SUPW chunk products (tree), Kogge-Stone over lanes, writes EXCLUSIVE prefix.
__global__ __launch_bounds__(128)
void kScan(int K, int SUPW, int NSUP) {
    int warp = (blockIdx.x * blockDim.x + threadIdx.x) >> 5;
    int lane = threadIdx.x & 31;
    if (warp >= BATCH) return;
    int b = warp;

    Frame f; frame_identity(f);
    if (lane < NSUP) {
        int k0 = lane * SUPW;
        int k1 = min(K, k0 + SUPW);
        int k = k0;
        bool first = true;
        while (k < k1) {
            Frame a; load_frame(g_chunk + (size_t)k * 12 * BATCH + b, a);
            if (k + 1 < k1) {
                Frame c2; load_frame(g_chunk + (size_t)(k + 1) * 12 * BATCH + b, c2);
                compose(a, c2);
                k += 2;
            } else {
                k += 1;
            }
            if (first) { f = a; first = false; }
            else       { compose(f, a); }
        }
    }

    #pragma unroll
    for (int d = 1; d < 32; d <<= 1) {
        Frame left = shfl_up_frame(f, d);
        Frame t = left;
        compose(t, f);
        if (lane >= d) f = t;
    }

    Frame ex = shfl_up_frame(f, 1);
    if (lane == 0) frame_identity(ex);

    if (lane < NSUP)
        store_frame(g_sprefix + (size_t)lane * 12 * BATCH + b, ex);
}

// Kernel C: assemble chunk prefix (superchunk prefix + warp-uniform fixup),
// replay the chunk, emit coordinates via smem-staged coalesced stores.
__global__ __launch_bounds__(128)
void kC(const float* __restrict__ dih, Geom gm, float* __restrict__ out,
        int K, int LRES, int SUPW) {
    __shared__ float s_out[4][3 * 96];   // [warp][point q][96 floats]
    int idx = blockIdx.x * blockDim.x + threadIdx.x;
    if (idx >= BATCH * K) return;
    int b = idx & (BATCH - 1);
    int k = idx >> 9;
    int ss = k / SUPW;
    int k0 = ss * SUPW;
    int lane = threadIdx.x & 31, wid = threadIdx.x >> 5;
    int b0 = b & ~31;

    float uxs[3], kks[3], Ls[3];
    chain_geom(gm, b, uxs, kks, Ls);

    Frame f;
    load_frame(g_sprefix + (size_t)ss * 12 * BATCH + b, f);
    for (int kk = k0; kk < k; kk++) {           // uniform across the warp
        Frame g; load_frame(g_chunk + (size_t)kk * 12 * BATCH + b, g);
        compose(f, g);
    }

    int l0 = k * CHUNK_RES;
    int l1 = min(LRES, l0 + CHUNK_RES);
    for (int l = l0; l < l1; l++) {
        const float* dp = dih + (size_t)l * (3 * BATCH) + b;
        float d0 = dp[0], d1 = dp[BATCH], d2 = dp[2 * BATCH];
        float s, c;
        float* sw = s_out[wid];

        __sincosf(d0, &s, &c); extend(f, s, c, uxs[0], kks[0], Ls[0]);
        sw[0 * 96 + lane * 3 + 0] = f.tx;
        sw[0 * 96 + lane * 3 + 1] = f.ty;
        sw[0 * 96 + lane * 3 + 2] = f.tz;
        __sincosf(d1, &s, &c); extend(f, s, c, uxs[1], kks[1], Ls[1]);
        sw[1 * 96 + lane * 3 + 0] = f.tx;
        sw[1 * 96 + lane * 3 + 1] = f.ty;
        sw[1 * 96 + lane * 3 + 2] = f.tz;
        __sincosf(d2, &s, &c); extend(f, s, c, uxs[2], kks[2], Ls[2]);
        sw[2 * 96 + lane * 3 + 0] = f.tx;
        sw[2 * 96 + lane * 3 + 1] = f.ty;
        sw[2 * 96 + lane * 3 + 2] = f.tz;
        __syncwarp();

        // Coalesced writeback: per point q, warp writes 96 contiguous floats.
        float* obase = out + ((size_t)(3 * l) * BATCH + b0) * 3;
        #pragma unroll
        for (int q = 0; q < 3; q++) {
            float* om = obase + (size_t)q * BATCH * 3;
            om[lane]      = sw[q * 96 + lane];
            om[lane + 32] = sw[q * 96 + lane + 32];
            om[lane + 64] = sw[q * 96 + lane + 64];
        }
        __syncwarp();
    }
}

extern "C" void kernel_launch(void* const* d_in, const int* in_sizes, int n_in,
                              void* d_out, int out_size) {
    const float* dih = (const float*)d_in[0];
    float* out = (float*)d_out;

    int Npts = in_sizes[0] / BATCH;
    int LRES = Npts / 3;
    int K = (LRES + CHUNK_RES - 1) / CHUNK_RES;
    if (K > MAXK) K = MAXK;
    int SUPW = (K + 31) / 32;
    int NSUP = (K + SUPW - 1) / SUPW;

    const double PI = 3.14159265358979323846;
    const float BL[3] = {145.801f, 152.326f, 132.868f};
    const float BA[3] = {2.124f, 1.941f, 2.028f};
    Geom gm;
    for (int d = 0; d < 3; d++) {
        double a  = PI - (double)BA[d];
        double rc = (double)BL[d] * cos(a);
        double rs = (double)BL[d] * sin(a);
        double L  = sqrt(rc * rc + rs * rs);
        gm.ux[d] = (float)(rc / L);
        gm.kk[d] = (float)(rs / L);
        gm.L[d]  = (float)L;
    }

    int nAC = BATCH * K;
    kA   <<<(nAC + 127) / 128, 128>>>(dih, gm, K, LRES);
    kScan<<<(BATCH * 32 + 127) / 128, 128>>>(K, SUPW, NSUP);
    kC   <<<(nAC + 127) / 128, 128>>>(dih, gm, out, K, LRES, SUPW);
}